// round 10
// baseline (speedup 1.0000x reference)
#include <cuda_runtime.h>
#include <cuda_bf16.h>
#include <cstdint>

#define N_NODES 50000
#define N_EDGES 800000
#define D_IN 128
#define D_HID 256
#define D_OUT 128

// ---------------- scratch (static device arrays; no allocation) ----------------
__device__ __nv_bfloat16 g_h1h[(size_t)N_NODES * D_HID];   // h1 hi     25.6 MB
__device__ __nv_bfloat16 g_h1l[(size_t)N_NODES * D_HID];   // h1 lo
__device__ float         g_t2[(size_t)N_NODES * D_OUT];    // 25.6 MB
__device__ __nv_bfloat16 g_w1th[D_HID * D_IN], g_w1tl[D_HID * D_IN];
__device__ __nv_bfloat16 g_w2th[D_OUT * D_HID], g_w2tl[D_OUT * D_HID];
__device__ int g_deg[N_NODES];
__device__ int g_off[N_NODES + 1];
__device__ int g_rank[N_EDGES];
__device__ int g_csr_src[N_EDGES];   // src node id  (layer-2 gather index)
__device__ int g_csr_c[N_EDGES];     // cncpt[src]   (layer-1 gather index)

// ================= small helpers =================
__device__ __forceinline__ uint32_t smem_u32(const void* p) {
    uint32_t a;
    asm("{ .reg .u64 t; cvta.to.shared.u64 t, %1; cvt.u32.u64 %0, t; }" : "=r"(a) : "l"(p));
    return a;
}

// split fp32 pair -> (hi bf16x2, lo bf16x2); low half of the b32 = first elem
__device__ __forceinline__ void split2(float a0, float a1, uint32_t& hi, uint32_t& lo) {
    asm("cvt.rn.bf16x2.f32 %0, %1, %2;" : "=r"(hi) : "f"(a1), "f"(a0));
    float h0 = __uint_as_float(hi << 16);
    float h1 = __uint_as_float(hi & 0xFFFF0000u);
    float l0 = a0 - h0, l1 = a1 - h1;
    asm("cvt.rn.bf16x2.f32 %0, %1, %2;" : "=r"(lo) : "f"(l1), "f"(l0));
}

__device__ __forceinline__ void ldsm_x4(uint32_t* r, uint32_t addr) {
    asm volatile("ldmatrix.sync.aligned.m8n8.x4.shared.b16 {%0,%1,%2,%3}, [%4];"
                 : "=r"(r[0]), "=r"(r[1]), "=r"(r[2]), "=r"(r[3]) : "r"(addr));
}

__device__ __forceinline__ void mma16816(float* d, const uint32_t* a, const uint32_t* b) {
    asm volatile("mma.sync.aligned.m16n8k16.row.col.f32.bf16.bf16.f32 "
                 "{%0,%1,%2,%3}, {%4,%5,%6,%7}, {%8,%9}, {%0,%1,%2,%3};"
                 : "+f"(d[0]), "+f"(d[1]), "+f"(d[2]), "+f"(d[3])
                 : "r"(a[0]), "r"(a[1]), "r"(a[2]), "r"(a[3]), "r"(b[0]), "r"(b[1]));
}

__device__ __forceinline__ void cp_async16(uint32_t dst, const void* src, int size) {
    asm volatile("cp.async.cg.shared.global [%0], [%1], 16, %2;"
                 :: "r"(dst), "l"(src), "r"(size) : "memory");
}

// swizzled smem byte offset within a plane: row stride 64B, chunk16 XOR (row>>1)&3
__device__ __forceinline__ uint32_t swz(int row, int chunk) {
    return (uint32_t)(row * 64 + ((chunk ^ ((row >> 1) & 3)) << 4));
}

// ================= CSR build =================
// histogram (2 edges/thread); records each edge's within-bucket rank
__global__ __launch_bounds__(256) void hist_dst(const int2* __restrict__ dst2) {
    int i = blockIdx.x * blockDim.x + threadIdx.x;
    if (i >= N_EDGES / 2) return;
    int2 d = dst2[i];
    int r0 = atomicAdd(&g_deg[d.x], 1);
    int r1 = atomicAdd(&g_deg[d.y], 1);
    *(int2*)&g_rank[2 * i] = make_int2(r0, r1);
}
__global__ __launch_bounds__(1024) void scan_deg() {
    __shared__ int sums[1024];
    const int CHUNK = (N_NODES + 1023) / 1024;
    int t = threadIdx.x;
    int lo = t * CHUNK;
    int hi = min(lo + CHUNK, N_NODES);
    int s = 0;
    for (int i = lo; i < hi; i++) s += g_deg[i];
    sums[t] = s;
    __syncthreads();
    for (int d = 1; d < 1024; d <<= 1) {
        int v = (t >= d) ? sums[t - d] : 0;
        __syncthreads();
        sums[t] += v;
        __syncthreads();
    }
    int running = sums[t] - s;
    for (int i = lo; i < hi; i++) {
        g_off[i] = running;
        running += g_deg[i];
    }
    if (t == 1023) g_off[N_NODES] = sums[1023];
}
// non-atomic scatter (2 edges/thread); also pre-composes cncpt[src] for layer-1
__global__ __launch_bounds__(256) void scatter_edges(
    const int2* __restrict__ src2, const int2* __restrict__ dst2,
    const int* __restrict__ cncpt)
{
    int i = blockIdx.x * blockDim.x + threadIdx.x;
    if (i >= N_EDGES / 2) return;
    int2 s = src2[i];
    int2 d = dst2[i];
    int2 r = *(const int2*)&g_rank[2 * i];
    int p0 = g_off[d.x] + r.x;
    int p1 = g_off[d.y] + r.y;
    int c0 = cncpt[s.x];
    int c1 = cncpt[s.y];
    g_csr_src[p0] = s.x;
    g_csr_src[p1] = s.y;
    g_csr_c[p0] = c0;
    g_csr_c[p1] = c1;
}

// ========== fused: zero degree + weight transpose/split (one launch) ==========
// NOTE: grid must cover max(N_NODES, D_HID*D_IN) threads!
__global__ void prep_all(const float* __restrict__ W1, const float* __restrict__ W2) {
    int i = blockIdx.x * blockDim.x + threadIdx.x;
    if (i < N_NODES) g_deg[i] = 0;
    if (i < D_HID * D_IN) {                  // W1^T [256][128]
        int n = i / D_IN, k = i % D_IN;
        float v = W1[(size_t)k * D_HID + n];
        __nv_bfloat16 h = __float2bfloat16_rn(v);
        g_w1th[i] = h;
        g_w1tl[i] = __float2bfloat16_rn(v - __bfloat162float(h));
    }
    if (i < D_OUT * D_HID) {                 // W2^T [128][256]
        int n = i / D_HID, k = i % D_HID;
        float v = W2[(size_t)k * D_OUT + n];
        __nv_bfloat16 h = __float2bfloat16_rn(v);
        g_w2th[i] = h;
        g_w2tl[i] = __float2bfloat16_rn(v - __bfloat162float(h));
    }
}

// ================= CSR aggregation (layer 2): warp per node, no atomics ==========
__global__ __launch_bounds__(256) void agg_csr2(
    const int* __restrict__ idx, const float4* __restrict__ rows,
    const float* __restrict__ bias, float4* __restrict__ outf)
{
    int w = (blockIdx.x * blockDim.x + threadIdx.x) >> 5;
    if (w >= N_NODES) return;
    int lane = threadIdx.x & 31;
    int beg = g_off[w], end = g_off[w + 1];

    float4 acc = make_float4(0.f, 0.f, 0.f, 0.f);
    int j = beg;
    for (; j + 8 <= end; j += 8) {
        int s[8];
#pragma unroll
        for (int q = 0; q < 8; q++) s[q] = idx[j + q];
        float4 v[8];
#pragma unroll
        for (int q = 0; q < 8; q++) v[q] = rows[(size_t)s[q] * 32 + lane];
#pragma unroll
        for (int q = 0; q < 8; q++) {
            acc.x += v[q].x; acc.y += v[q].y; acc.z += v[q].z; acc.w += v[q].w;
        }
    }
    for (; j < end; j++) {
        float4 v = rows[(size_t)idx[j] * 32 + lane];
        acc.x += v.x; acc.y += v.y; acc.z += v.z; acc.w += v.w;
    }
    float4 b = ((const float4*)bias)[lane];
    acc.x = fmaxf(acc.x + b.x, 0.f);
    acc.y = fmaxf(acc.y + b.y, 0.f);
    acc.z = fmaxf(acc.z + b.z, 0.f);
    acc.w = fmaxf(acc.w + b.w, 0.f);
    outf[(size_t)w * 32 + lane] = acc;
}

// ========== FUSED layer-1: CSR aggregation + split + HMMA GEMM ==========
// CTA handles 64 nodes x full N=256. Phase 1: warp-per-node gather-sum from emb
// (indices = pre-composed concept ids), split-bf16 into smem-resident A planes.
// Phase 2: K-loop (4 chunks of 32) with B (W1^T) double-buffered via cp.async,
// prefetched BEFORE phase 1 so B loads overlap the aggregation.
// Epilogue: bias+relu, write h1 as split-bf16 planes.
__global__ __launch_bounds__(256, 2) void fused_agg_gemm1(
    const float4* __restrict__ emb,
    const __nv_bfloat16* __restrict__ Bh, const __nv_bfloat16* __restrict__ Bl,
    const float* __restrict__ bias,
    __nv_bfloat16* __restrict__ Ch, __nv_bfloat16* __restrict__ Cl, int M)
{
    constexpr int KK = 128, NN = 256, NC = 4;
    constexpr int AH_OFF = 0;              // 4 chunk-planes x (64 rows x 64B) = 16KB
    constexpr int AL_OFF = 16384;
    constexpr int B_OFF  = 32768;          // 2 stages x (BH 16KB + BL 16KB)
    constexpr int BSTAGE = 32768;
    extern __shared__ __align__(16) char smem[];   // 96KB

    const int tid  = threadIdx.x;
    const int wid  = tid >> 5;
    const int lane = tid & 31;
    const int wm   = wid & 1;              // 2 warps along M (32 rows each)
    const int wn   = wid >> 1;             // 4 warps along N (64 cols each)
    const int blockM = blockIdx.x * 64;
    const uint32_t sb0 = smem_u32(smem);

    // ---- B stage loader: 2 planes x 256 rows x 4 chunks = 2048 x 16B ----
    auto load_B = [&](int s, int kc) {
        uint32_t sb = sb0 + B_OFF + (uint32_t)s * BSTAGE;
#pragma unroll
        for (int i = 0; i < 8; i++) {
            int g   = i * 256 + tid;
            int p   = g >> 10;
            int idx = g & 1023;
            int row = idx >> 2, c = idx & 3;
            const __nv_bfloat16* src =
                (p ? Bl : Bh) + (size_t)row * KK + kc * 32 + c * 8;
            cp_async16(sb + (uint32_t)p * 16384 + swz(row, c), src, 16);
        }
        asm volatile("cp.async.commit_group;" ::: "memory");
    };

    // prefetch both B stages before aggregation (overlaps phase 1)
    load_B(0, 0);
    load_B(1, 1);

    // ---- Phase 1: aggregate 8 nodes per warp, write split-bf16 A planes ----
#pragma unroll 1
    for (int t = 0; t < 8; t++) {
        int r = wid * 8 + t;               // CTA-local row 0..63
        int node = blockM + r;
        int beg = 0, end = 0;
        if (node < M) { beg = g_off[node]; end = g_off[node + 1]; }

        float4 acc = make_float4(0.f, 0.f, 0.f, 0.f);
        int j = beg;
        for (; j + 8 <= end; j += 8) {
            int s[8];
#pragma unroll
            for (int q = 0; q < 8; q++) s[q] = g_csr_c[j + q];
            float4 v[8];
#pragma unroll
            for (int q = 0; q < 8; q++) v[q] = emb[(size_t)s[q] * 32 + lane];
#pragma unroll
            for (int q = 0; q < 8; q++) {
                acc.x += v[q].x; acc.y += v[q].y; acc.z += v[q].z; acc.w += v[q].w;
            }
        }
        for (; j < end; j++) {
            float4 v = emb[(size_t)g_csr_c[j] * 32 + lane];
            acc.x += v.x; acc.y += v.y; acc.z += v.z; acc.w += v.w;
        }
        uint32_t h0, l0, h1, l1;
        split2(acc.x, acc.y, h0, l0);
        split2(acc.z, acc.w, h1, l1);
        // byte col = lane*8 within the 256B row -> plane (lane>>3), chunk (lane&7)>>1, sub (lane&1)*8
        uint32_t off = (uint32_t)((lane >> 3) * 4096) + swz(r, (lane & 7) >> 1) + (lane & 1) * 8;
        *(uint2*)(smem + AH_OFF + off) = make_uint2(h0, h1);
        *(uint2*)(smem + AL_OFF + off) = make_uint2(l0, l1);
    }
    __syncthreads();

    // ---- Phase 2: K-loop, A resident, B double-buffered ----
    const int a_row = wm * 32 + (lane & 15);
    const int a_chk = lane >> 4;
    const int b_row = wn * 64 + ((lane >> 4) << 3) + (lane & 7);
    const int b_chk = (lane >> 3) & 1;

    float acc[2][8][4];
#pragma unroll
    for (int mt = 0; mt < 2; mt++)
#pragma unroll
        for (int j = 0; j < 8; j++)
#pragma unroll
            for (int q = 0; q < 4; q++) acc[mt][j][q] = 0.f;

    for (int kc = 0; kc < NC; kc++) {
        if (kc < NC - 1) asm volatile("cp.async.wait_group 1;" ::: "memory");
        else             asm volatile("cp.async.wait_group 0;" ::: "memory");
        __syncthreads();

        const uint32_t abase = sb0 + (uint32_t)(kc * 4096);
        const uint32_t bbase = sb0 + B_OFF + (uint32_t)((kc & 1) * BSTAGE);
#pragma unroll
        for (int kh = 0; kh < 2; kh++) {
            uint32_t ah[2][4], al[2][4];
#pragma unroll
            for (int mt = 0; mt < 2; mt++) {
                uint32_t off = swz(a_row + mt * 16, kh * 2 + a_chk);
                ldsm_x4(ah[mt], abase + AH_OFF + off);
                ldsm_x4(al[mt], abase + AL_OFF + off);
            }
#pragma unroll
            for (int jj = 0; jj < 4; jj++) {
                uint32_t off = swz(b_row + jj * 16, kh * 2 + b_chk);
                uint32_t tb[4], tl[4];
                ldsm_x4(tb, bbase + off);
                ldsm_x4(tl, bbase + 16384 + off);
                const int j0 = 2 * jj, j1 = 2 * jj + 1;
                mma16816(acc[0][j0], ah[0], tb + 0);
                mma16816(acc[1][j0], ah[1], tb + 0);
                mma16816(acc[0][j1], ah[0], tb + 2);
                mma16816(acc[1][j1], ah[1], tb + 2);
                mma16816(acc[0][j0], ah[0], tl + 0);
                mma16816(acc[1][j0], ah[1], tl + 0);
                mma16816(acc[0][j1], ah[0], tl + 2);
                mma16816(acc[1][j1], ah[1], tl + 2);
                mma16816(acc[0][j0], al[0], tb + 0);
                mma16816(acc[1][j0], al[1], tb + 0);
                mma16816(acc[0][j1], al[0], tb + 2);
                mma16816(acc[1][j1], al[1], tb + 2);
            }
        }
        __syncthreads();
        if (kc + 2 < NC) load_B(kc & 1, kc + 2);
    }

    // ---- epilogue: bias + relu, split-bf16 h1 ----
    const int m_base = blockM + wm * 32 + (lane >> 2);
    const int n_base = wn * 64 + 2 * (lane & 3);
#pragma unroll
    for (int mt = 0; mt < 2; mt++) {
#pragma unroll
        for (int j = 0; j < 8; j++) {
            int n = n_base + 8 * j;
            float2 v0 = make_float2(acc[mt][j][0], acc[mt][j][1]);
            float2 v1 = make_float2(acc[mt][j][2], acc[mt][j][3]);
            float bb0 = bias[n], bb1 = bias[n + 1];
            v0.x = fmaxf(v0.x + bb0, 0.f); v0.y = fmaxf(v0.y + bb1, 0.f);
            v1.x = fmaxf(v1.x + bb0, 0.f); v1.y = fmaxf(v1.y + bb1, 0.f);
            int m = m_base + mt * 16;
            uint32_t h, l;
            if (m < M) {
                split2(v0.x, v0.y, h, l);
                *(uint32_t*)(Ch + (size_t)m * NN + n) = h;
                *(uint32_t*)(Cl + (size_t)m * NN + n) = l;
            }
            if (m + 8 < M) {
                split2(v1.x, v1.y, h, l);
                *(uint32_t*)(Ch + (size_t)(m + 8) * NN + n) = h;
                *(uint32_t*)(Cl + (size_t)(m + 8) * NN + n) = l;
            }
        }
    }
}

// ================= HMMA split-bf16 GEMM (layer 2), cp.async double-buffered ====
// C[M,128] = (Ah+Al)[M,256] @ (Bh+Bl)[128,256]^T, BM=64, fp32 out.
__global__ __launch_bounds__(256, 2) void hmma_gemm2(
    const __nv_bfloat16* __restrict__ Ah, const __nv_bfloat16* __restrict__ Al,
    const __nv_bfloat16* __restrict__ Bh, const __nv_bfloat16* __restrict__ Bl,
    float* __restrict__ Cf, int M)
{
    constexpr int BM = 64, NN = 128, KK = 256;
    constexpr int APLANE_B = BM * 64;
    constexpr int BPLANE_B = 128 * 64;
    constexpr int STAGE_B  = 2 * APLANE_B + 2 * BPLANE_B;   // 24KB
    constexpr int ITERS    = (2 * BM + 256) * 4 / 256;      // 6
    extern __shared__ __align__(16) char smem[];            // [2][STAGE_B]

    const int tid  = threadIdx.x;
    const int wid  = tid >> 5;
    const int lane = tid & 31;
    const int wm   = wid & 1;              // 2 warps along M
    const int wn   = wid >> 1;             // 4 warps along N (32 cols each)
    const int blockM = blockIdx.x * BM;
    const uint32_t sb0 = smem_u32(smem);

    const int a_row = wm * 32 + (lane & 15);
    const int a_chk = lane >> 4;
    const int b_row = wn * 32 + ((lane >> 4) << 3) + (lane & 7);
    const int b_chk = (lane >> 3) & 1;

    float acc[2][4][4];
#pragma unroll
    for (int mt = 0; mt < 2; mt++)
#pragma unroll
        for (int j = 0; j < 4; j++)
#pragma unroll
            for (int q = 0; q < 4; q++) acc[mt][j][q] = 0.f;

    auto load_stage = [&](int s, int kc) {
        uint32_t sb = sb0 + (uint32_t)s * STAGE_B;
#pragma unroll
        for (int i = 0; i < ITERS; i++) {
            int g = i * 256 + tid;
            const __nv_bfloat16* src;
            uint32_t dst;
            int size = 16;
            if (g < 2 * BM * 4) {
                int p   = g >= BM * 4;
                int idx = g - p * BM * 4;
                int row = idx >> 2, c = idx & 3;
                int gm = blockM + row;
                int cm = gm < M ? gm : 0;
                if (gm >= M) size = 0;
                src = (p ? Al : Ah) + (size_t)cm * KK + kc + c * 8;
                dst = sb + (uint32_t)(p * APLANE_B) + swz(row, c);
            } else {
                int gb  = g - 8 * BM;
                int p   = gb >> 9;
                int idx = gb & 511;
                int row = idx >> 2, c = idx & 3;
                src = (p ? Bl : Bh) + (size_t)row * KK + kc + c * 8;
                dst = sb + (uint32_t)(2 * APLANE_B + p * BPLANE_B) + swz(row, c);
            }
            cp_async16(dst, src, size);
        }
        asm volatile("cp.async.commit_group;" ::: "memory");
    };

    constexpr int NC = KK / 32;
    load_stage(0, 0);

    for (int c = 0; c < NC; c++) {
        if (c + 1 < NC) {
            load_stage((c + 1) & 1, (c + 1) * 32);
            asm volatile("cp.async.wait_group 1;" ::: "memory");
        } else {
            asm volatile("cp.async.wait_group 0;" ::: "memory");
        }
        __syncthreads();

        const uint32_t base = sb0 + (uint32_t)(c & 1) * STAGE_B;
#pragma unroll
        for (int kh = 0; kh < 2; kh++) {
            uint32_t ah[2][4], al[2][4];
#pragma unroll
            for (int mt = 0; mt < 2; mt++) {
                uint32_t off = swz(a_row + mt * 16, kh * 2 + a_chk);
                ldsm_x4(ah[mt], base + off);
                ldsm_x4(al[mt], base + APLANE_B + off);
            }
#pragma unroll
            for (int jj = 0; jj < 2; jj++) {
                uint32_t off = 2 * APLANE_B + swz(b_row + jj * 16, kh * 2 + b_chk);
                uint32_t tb[4], tl[4];
                ldsm_x4(tb, base + off);
                ldsm_x4(tl, base + BPLANE_B + off);
                const int j0 = 2 * jj, j1 = 2 * jj + 1;
                mma16816(acc[0][j0], ah[0], tb + 0);
                mma16816(acc[1][j0], ah[1], tb + 0);
                mma16816(acc[0][j1], ah[0], tb + 2);
                mma16816(acc[1][j1], ah[1], tb + 2);
                mma16816(acc[0][j0], ah[0], tl + 0);
                mma16816(acc[1][j0], ah[1], tl + 0);
                mma16816(acc[0][j1], ah[0], tl + 2);
                mma16816(acc[1][j1], ah[1], tl + 2);
                mma16816(acc[0][j0], al[0], tb + 0);
                mma16816(acc[1][j0], al[1], tb + 0);
                mma16816(acc[0][j1], al[0], tb + 2);
                mma16816(acc[1][j1], al[1], tb + 2);
            }
        }
        __syncthreads();
    }

    const int m_base = blockM + wm * 32 + (lane >> 2);
    const int n_base = wn * 32 + 2 * (lane & 3);
#pragma unroll
    for (int mt = 0; mt < 2; mt++) {
#pragma unroll
        for (int j = 0; j < 4; j++) {
            int n = n_base + 8 * j;
            float2 v0 = make_float2(acc[mt][j][0], acc[mt][j][1]);
            float2 v1 = make_float2(acc[mt][j][2], acc[mt][j][3]);
            int m = m_base + mt * 16;
            if (m < M)     *(float2*)(Cf + (size_t)m * NN + n)       = v0;
            if (m + 8 < M) *(float2*)(Cf + (size_t)(m + 8) * NN + n) = v1;
        }
    }
}

// ---------------- launch ----------------
extern "C" void kernel_launch(void* const* d_in, const int* in_sizes, int n_in,
                              void* d_out, int out_size) {
    const int*   cncpt = (const int*)d_in[0];
    const int*   src   = (const int*)d_in[1];
    const int*   dst   = (const int*)d_in[2];
    const float* emb   = (const float*)d_in[3];
    const float* W1    = (const float*)d_in[4];
    const float* b1    = (const float*)d_in[5];
    const float* W2    = (const float*)d_in[6];
    const float* b2    = (const float*)d_in[7];
    float* out = (float*)d_out;

    __nv_bfloat16 *h1h, *h1l, *w1th, *w1tl, *w2th, *w2tl;
    float *t2;
    int *csr_src;
    cudaGetSymbolAddress((void**)&h1h,  g_h1h);
    cudaGetSymbolAddress((void**)&h1l,  g_h1l);
    cudaGetSymbolAddress((void**)&t2,   g_t2);
    cudaGetSymbolAddress((void**)&w1th, g_w1th);
    cudaGetSymbolAddress((void**)&w1tl, g_w1tl);
    cudaGetSymbolAddress((void**)&w2th, g_w2th);
    cudaGetSymbolAddress((void**)&w2tl, g_w2tl);
    cudaGetSymbolAddress((void**)&csr_src, g_csr_src);

    const int SMEM1 = 96 * 1024;                         // fused kernel
    const int SMEM2 = 2 * (2 * 64 * 64 + 2 * 128 * 64);  // 49152 B
    cudaFuncSetAttribute(fused_agg_gemm1,
                         cudaFuncAttributeMaxDynamicSharedMemorySize, SMEM1);
    cudaFuncSetAttribute(hmma_gemm2,
                         cudaFuncAttributeMaxDynamicSharedMemorySize, SMEM2);

    // ---- prep: zero degree + weight transpose/split (one launch) ----
    // grid MUST cover max(N_NODES, D_HID*D_IN) threads (R9 bug: covered only 32768)
    const int prep_n = (N_NODES > D_HID * D_IN ? N_NODES : D_HID * D_IN);
    prep_all<<<(prep_n + 255) / 256, 256>>>(W1, W2);

    // ---- build CSR (by dst) ----
    hist_dst<<<(N_EDGES / 2 + 255) / 256, 256>>>((const int2*)dst);
    scan_deg<<<1, 1024>>>();
    scatter_edges<<<(N_EDGES / 2 + 255) / 256, 256>>>(
        (const int2*)src, (const int2*)dst, cncpt);

    // ---- layer 1: fused aggregation + GEMM (h1 = relu(agg(emb) @ W1 + b1)) ----
    fused_agg_gemm1<<<(N_NODES + 63) / 64, 256, SMEM1>>>(
        (const float4*)emb, w1th, w1tl, b1, h1h, h1l, N_NODES);

    // ---- t2 = h1 @ W2 (GEMM commuted before aggregation) ----
    hmma_gemm2<<<(N_NODES + 63) / 64, 256, SMEM2>>>(
        h1h, h1l, w2th, w2tl, t2, N_NODES);

    // ---- layer 2 aggregation + bias + relu into d_out ----
    agg_csr2<<<(N_NODES * 32 + 255) / 256, 256>>>(
        csr_src, (const float4*)t2, b2, (float4*)out);
}

// round 11
// speedup vs baseline: 1.1884x; 1.1884x over previous
#include <cuda_runtime.h>
#include <cuda_bf16.h>
#include <cstdint>

#define N_NODES 50000
#define N_EDGES 800000
#define D_IN 128
#define D_HID 256
#define D_OUT 128

// ---------------- scratch (static device arrays; no allocation) ----------------
__device__ __nv_bfloat16 g_a1h[(size_t)N_NODES * D_IN];    // agg1 hi  12.8 MB
__device__ __nv_bfloat16 g_a1l[(size_t)N_NODES * D_IN];    // agg1 lo
__device__ float         g_t2[(size_t)N_NODES * D_OUT];    // 25.6 MB
__device__ __nv_bfloat16 g_w1th[D_HID * D_IN], g_w1tl[D_HID * D_IN];
__device__ __nv_bfloat16 g_w2th[D_OUT * D_HID], g_w2tl[D_OUT * D_HID];
__device__ int g_deg[N_NODES];
__device__ int g_off[N_NODES + 1];
__device__ int g_rank[N_EDGES];
__device__ int g_csr_src[N_EDGES];   // src node id  (layer-2 gather index)
__device__ int g_csr_c[N_EDGES];     // cncpt[src]   (layer-1 gather index)

// ================= small helpers =================
__device__ __forceinline__ uint32_t smem_u32(const void* p) {
    uint32_t a;
    asm("{ .reg .u64 t; cvta.to.shared.u64 t, %1; cvt.u32.u64 %0, t; }" : "=r"(a) : "l"(p));
    return a;
}

// split fp32 pair -> (hi bf16x2, lo bf16x2); low half of the b32 = first elem
__device__ __forceinline__ void split2(float a0, float a1, uint32_t& hi, uint32_t& lo) {
    asm("cvt.rn.bf16x2.f32 %0, %1, %2;" : "=r"(hi) : "f"(a1), "f"(a0));
    float h0 = __uint_as_float(hi << 16);
    float h1 = __uint_as_float(hi & 0xFFFF0000u);
    float l0 = a0 - h0, l1 = a1 - h1;
    asm("cvt.rn.bf16x2.f32 %0, %1, %2;" : "=r"(lo) : "f"(l1), "f"(l0));
}

__device__ __forceinline__ void ldsm_x4(uint32_t* r, uint32_t addr) {
    asm volatile("ldmatrix.sync.aligned.m8n8.x4.shared.b16 {%0,%1,%2,%3}, [%4];"
                 : "=r"(r[0]), "=r"(r[1]), "=r"(r[2]), "=r"(r[3]) : "r"(addr));
}

__device__ __forceinline__ void mma16816(float* d, const uint32_t* a, const uint32_t* b) {
    asm volatile("mma.sync.aligned.m16n8k16.row.col.f32.bf16.bf16.f32 "
                 "{%0,%1,%2,%3}, {%4,%5,%6,%7}, {%8,%9}, {%0,%1,%2,%3};"
                 : "+f"(d[0]), "+f"(d[1]), "+f"(d[2]), "+f"(d[3])
                 : "r"(a[0]), "r"(a[1]), "r"(a[2]), "r"(a[3]), "r"(b[0]), "r"(b[1]));
}

__device__ __forceinline__ void cp_async16(uint32_t dst, const void* src, int size) {
    asm volatile("cp.async.cg.shared.global [%0], [%1], 16, %2;"
                 :: "r"(dst), "l"(src), "r"(size) : "memory");
}

// swizzled smem byte offset within a plane: row stride 64B, chunk16 XOR (row>>1)&3
__device__ __forceinline__ uint32_t swz(int row, int chunk) {
    return (uint32_t)(row * 64 + ((chunk ^ ((row >> 1) & 3)) << 4));
}

// ================= CSR build =================
// histogram (2 edges/thread); records each edge's within-bucket rank
__global__ __launch_bounds__(256) void hist_dst(const int2* __restrict__ dst2) {
    int i = blockIdx.x * blockDim.x + threadIdx.x;
    if (i >= N_EDGES / 2) return;
    int2 d = dst2[i];
    int r0 = atomicAdd(&g_deg[d.x], 1);
    int r1 = atomicAdd(&g_deg[d.y], 1);
    *(int2*)&g_rank[2 * i] = make_int2(r0, r1);
}
__global__ __launch_bounds__(1024) void scan_deg() {
    __shared__ int sums[1024];
    const int CHUNK = (N_NODES + 1023) / 1024;
    int t = threadIdx.x;
    int lo = t * CHUNK;
    int hi = min(lo + CHUNK, N_NODES);
    int s = 0;
    for (int i = lo; i < hi; i++) s += g_deg[i];
    sums[t] = s;
    __syncthreads();
    for (int d = 1; d < 1024; d <<= 1) {
        int v = (t >= d) ? sums[t - d] : 0;
        __syncthreads();
        sums[t] += v;
        __syncthreads();
    }
    int running = sums[t] - s;
    for (int i = lo; i < hi; i++) {
        g_off[i] = running;
        running += g_deg[i];
    }
    if (t == 1023) g_off[N_NODES] = sums[1023];
}
// non-atomic scatter (2 edges/thread); also pre-composes cncpt[src] for layer-1
__global__ __launch_bounds__(256) void scatter_edges(
    const int2* __restrict__ src2, const int2* __restrict__ dst2,
    const int* __restrict__ cncpt)
{
    int i = blockIdx.x * blockDim.x + threadIdx.x;
    if (i >= N_EDGES / 2) return;
    int2 s = src2[i];
    int2 d = dst2[i];
    int2 r = *(const int2*)&g_rank[2 * i];
    int p0 = g_off[d.x] + r.x;
    int p1 = g_off[d.y] + r.y;
    int c0 = cncpt[s.x];
    int c1 = cncpt[s.y];
    g_csr_src[p0] = s.x;
    g_csr_src[p1] = s.y;
    g_csr_c[p0] = c0;
    g_csr_c[p1] = c1;
}

// ========== fused: zero degree + weight transpose/split (one launch) ==========
// grid must cover max(N_NODES, D_HID*D_IN) threads
__global__ void prep_all(const float* __restrict__ W1, const float* __restrict__ W2) {
    int i = blockIdx.x * blockDim.x + threadIdx.x;
    if (i < N_NODES) g_deg[i] = 0;
    if (i < D_HID * D_IN) {                  // W1^T [256][128]
        int n = i / D_IN, k = i % D_IN;
        float v = W1[(size_t)k * D_HID + n];
        __nv_bfloat16 h = __float2bfloat16_rn(v);
        g_w1th[i] = h;
        g_w1tl[i] = __float2bfloat16_rn(v - __bfloat162float(h));
    }
    if (i < D_OUT * D_HID) {                 // W2^T [128][256]
        int n = i / D_HID, k = i % D_HID;
        float v = W2[(size_t)k * D_OUT + n];
        __nv_bfloat16 h = __float2bfloat16_rn(v);
        g_w2th[i] = h;
        g_w2tl[i] = __float2bfloat16_rn(v - __bfloat162float(h));
    }
}

// ================= CSR aggregation: warp per node, no atomics =================
// SPLIT: write hi/lo bf16 planes. else: fp32 out (+bias+relu).
template<bool EPI, bool SPLIT>
__global__ __launch_bounds__(256) void agg_csr(
    const int* __restrict__ idx, const float4* __restrict__ rows,
    const float* __restrict__ bias, float4* __restrict__ outf,
    __nv_bfloat16* __restrict__ oh, __nv_bfloat16* __restrict__ ol)
{
    int w = (blockIdx.x * blockDim.x + threadIdx.x) >> 5;
    if (w >= N_NODES) return;
    int lane = threadIdx.x & 31;
    int beg = g_off[w], end = g_off[w + 1];

    float4 acc = make_float4(0.f, 0.f, 0.f, 0.f);
    int j = beg;
    for (; j + 8 <= end; j += 8) {
        int s[8];
#pragma unroll
        for (int q = 0; q < 8; q++) s[q] = idx[j + q];
        float4 v[8];
#pragma unroll
        for (int q = 0; q < 8; q++) v[q] = rows[(size_t)s[q] * 32 + lane];
#pragma unroll
        for (int q = 0; q < 8; q++) {
            acc.x += v[q].x; acc.y += v[q].y; acc.z += v[q].z; acc.w += v[q].w;
        }
    }
    for (; j < end; j++) {
        float4 v = rows[(size_t)idx[j] * 32 + lane];
        acc.x += v.x; acc.y += v.y; acc.z += v.z; acc.w += v.w;
    }
    if (EPI) {
        float4 b = ((const float4*)bias)[lane];
        acc.x = fmaxf(acc.x + b.x, 0.f);
        acc.y = fmaxf(acc.y + b.y, 0.f);
        acc.z = fmaxf(acc.z + b.z, 0.f);
        acc.w = fmaxf(acc.w + b.w, 0.f);
    }
    if (SPLIT) {
        uint32_t h0, l0, h1, l1;
        split2(acc.x, acc.y, h0, l0);
        split2(acc.z, acc.w, h1, l1);
        size_t off = (size_t)w * 128 + lane * 4;
        *(uint2*)(oh + off) = make_uint2(h0, h1);
        *(uint2*)(ol + off) = make_uint2(l0, l1);
    } else {
        outf[(size_t)w * 32 + lane] = acc;
    }
}

// ========== FUSED GEMM1+GEMM2: t2[64x128] = relu(A1[64x128]@W1T^T + b1) @ W2T^T ==========
// Phase A: h = relu(A1 @ W1T^T + b1), acc in registers (A1 smem-resident, W1
// double-buffered). h restaged to smem as split-bf16 K-chunk planes. Phase B:
// t2 = h @ W2T^T with W2 double-buffered. h1 never touches global memory.
// smem (96KB): phase A [A1 hi16K|lo16K][W1 2x(hi16K|lo16K)]
//              phase B [H hi32K|lo32K][W2 2x(hi8K|lo8K)]
__global__ __launch_bounds__(256, 2) void fused_gemm12(
    const __nv_bfloat16* __restrict__ A1h, const __nv_bfloat16* __restrict__ A1l,
    const __nv_bfloat16* __restrict__ B1h, const __nv_bfloat16* __restrict__ B1l,
    const __nv_bfloat16* __restrict__ B2h, const __nv_bfloat16* __restrict__ B2l,
    const float* __restrict__ bias1, float* __restrict__ t2, int M)
{
    constexpr int B1_OFF = 32768;
    constexpr int B2_OFF = 65536;
    extern __shared__ __align__(16) char smem[];
    const uint32_t sb0 = smem_u32(smem);

    const int tid  = threadIdx.x;
    const int wid  = tid >> 5;
    const int lane = tid & 31;
    const int wm   = wid & 1;              // 2 warps along M (32 rows each)
    const int wn   = wid >> 1;             // 4 warps along N
    const int blockM = blockIdx.x * 64;

    const int a_row = wm * 32 + (lane & 15);
    const int a_chk = lane >> 4;
    const int b_row1 = wn * 64 + ((lane >> 4) << 3) + (lane & 7);   // phase A (256 rows)
    const int b_row2 = wn * 32 + ((lane >> 4) << 3) + (lane & 7);   // phase B (128 rows)
    const int b_chk = (lane >> 3) & 1;

    // ---- group 1: A1 tile 64x128 hi/lo (2048 x 16B) ----
    {
#pragma unroll
        for (int i = 0; i < 8; i++) {
            int g = i * 256 + tid;
            int p = g >> 10;
            int idx = g & 1023;
            int r = idx >> 4, q = idx & 15;
            int gm = blockM + r;
            int cm = gm < M ? gm : 0;
            int size = gm < M ? 16 : 0;
            const __nv_bfloat16* src = (p ? A1l : A1h) + (size_t)cm * 128 + q * 8;
            cp_async16(sb0 + (uint32_t)(p * 16384 + (q >> 2) * 4096) + swz(r, q & 3),
                       src, size);
        }
        asm volatile("cp.async.commit_group;" ::: "memory");
    }

    // ---- W1 stage loader: 256 rows x 64B x 2 planes (2048 x 16B) ----
    auto load_B1 = [&](int s, int kc) {
        uint32_t sb = sb0 + B1_OFF + (uint32_t)s * 32768;
#pragma unroll
        for (int i = 0; i < 8; i++) {
            int g = i * 256 + tid;
            int p = g >> 10;
            int idx = g & 1023;
            int row = idx >> 2, c = idx & 3;
            const __nv_bfloat16* src = (p ? B1l : B1h) + (size_t)row * 128 + kc * 32 + c * 8;
            cp_async16(sb + (uint32_t)p * 16384 + swz(row, c), src, 16);
        }
        asm volatile("cp.async.commit_group;" ::: "memory");
    };
    load_B1(0, 0);
    load_B1(1, 1);

    float acc1[2][8][4];
#pragma unroll
    for (int mt = 0; mt < 2; mt++)
#pragma unroll
        for (int j = 0; j < 8; j++)
#pragma unroll
            for (int q = 0; q < 4; q++) acc1[mt][j][q] = 0.f;

    // ---- Phase A mainloop: 4 K-chunks ----
    for (int kc = 0; kc < 4; kc++) {
        if (kc < 3) asm volatile("cp.async.wait_group 1;" ::: "memory");
        else        asm volatile("cp.async.wait_group 0;" ::: "memory");
        __syncthreads();

        const uint32_t abase = sb0 + (uint32_t)(kc * 4096);
        const uint32_t bbase = sb0 + B1_OFF + (uint32_t)((kc & 1) * 32768);
#pragma unroll
        for (int kh = 0; kh < 2; kh++) {
            uint32_t ah[2][4], al[2][4];
#pragma unroll
            for (int mt = 0; mt < 2; mt++) {
                uint32_t off = swz(a_row + mt * 16, kh * 2 + a_chk);
                ldsm_x4(ah[mt], abase + off);
                ldsm_x4(al[mt], abase + 16384 + off);
            }
#pragma unroll
            for (int jj = 0; jj < 4; jj++) {
                uint32_t off = swz(b_row1 + jj * 16, kh * 2 + b_chk);
                uint32_t tb[4], tl[4];
                ldsm_x4(tb, bbase + off);
                ldsm_x4(tl, bbase + 16384 + off);
                const int j0 = 2 * jj, j1 = 2 * jj + 1;
                mma16816(acc1[0][j0], ah[0], tb + 0);
                mma16816(acc1[1][j0], ah[1], tb + 0);
                mma16816(acc1[0][j1], ah[0], tb + 2);
                mma16816(acc1[1][j1], ah[1], tb + 2);
                mma16816(acc1[0][j0], ah[0], tl + 0);
                mma16816(acc1[1][j0], ah[1], tl + 0);
                mma16816(acc1[0][j1], ah[0], tl + 2);
                mma16816(acc1[1][j1], ah[1], tl + 2);
                mma16816(acc1[0][j0], al[0], tb + 0);
                mma16816(acc1[1][j0], al[1], tb + 0);
                mma16816(acc1[0][j1], al[0], tb + 2);
                mma16816(acc1[1][j1], al[1], tb + 2);
            }
        }
        __syncthreads();
        if (kc + 2 < 4) load_B1(kc & 1, kc + 2);
    }

    // ---- W2 stage loader: 128 rows x 64B x 2 planes (1024 x 16B) ----
    auto load_B2 = [&](int s, int kc) {
        uint32_t sb = sb0 + B2_OFF + (uint32_t)s * 16384;
#pragma unroll
        for (int i = 0; i < 4; i++) {
            int g = i * 256 + tid;
            int p = g >> 9;
            int idx = g & 511;
            int row = idx >> 2, c = idx & 3;
            const __nv_bfloat16* src = (p ? B2l : B2h) + (size_t)row * 256 + kc * 32 + c * 8;
            cp_async16(sb + (uint32_t)p * 8192 + swz(row, c), src, 16);
        }
        asm volatile("cp.async.commit_group;" ::: "memory");
    };
    load_B2(0, 0);
    load_B2(1, 1);

    // ---- transition: bias+relu, restage h as split-bf16 K-chunk planes ----
    {
        const int m_loc = wm * 32 + (lane >> 2);
        const int n_loc = wn * 64 + 2 * (lane & 3);
#pragma unroll
        for (int mt = 0; mt < 2; mt++) {
#pragma unroll
            for (int j = 0; j < 8; j++) {
                int n = n_loc + 8 * j;
                float bb0 = bias1[n], bb1 = bias1[n + 1];
                float2 v0 = make_float2(fmaxf(acc1[mt][j][0] + bb0, 0.f),
                                        fmaxf(acc1[mt][j][1] + bb1, 0.f));
                float2 v1 = make_float2(fmaxf(acc1[mt][j][2] + bb0, 0.f),
                                        fmaxf(acc1[mt][j][3] + bb1, 0.f));
                uint32_t kc2 = (uint32_t)(n >> 5) * 4096;
                uint32_t bc = (uint32_t)(n & 31) * 2;
                uint32_t chk = bc >> 4, rem = bc & 12;
                int r0 = m_loc + mt * 16, r1 = r0 + 8;
                uint32_t h, l;
                split2(v0.x, v0.y, h, l);
                *(uint32_t*)(smem + kc2 + swz(r0, chk) + rem) = h;
                *(uint32_t*)(smem + 32768 + kc2 + swz(r0, chk) + rem) = l;
                split2(v1.x, v1.y, h, l);
                *(uint32_t*)(smem + kc2 + swz(r1, chk) + rem) = h;
                *(uint32_t*)(smem + 32768 + kc2 + swz(r1, chk) + rem) = l;
            }
        }
    }
    __syncthreads();

    // ---- Phase B mainloop: 8 K-chunks ----
    float acc2[2][4][4];
#pragma unroll
    for (int mt = 0; mt < 2; mt++)
#pragma unroll
        for (int j = 0; j < 4; j++)
#pragma unroll
            for (int q = 0; q < 4; q++) acc2[mt][j][q] = 0.f;

    for (int kc = 0; kc < 8; kc++) {
        if (kc < 7) asm volatile("cp.async.wait_group 1;" ::: "memory");
        else        asm volatile("cp.async.wait_group 0;" ::: "memory");
        __syncthreads();

        const uint32_t abase = sb0 + (uint32_t)(kc * 4096);
        const uint32_t bbase = sb0 + B2_OFF + (uint32_t)((kc & 1) * 16384);
#pragma unroll
        for (int kh = 0; kh < 2; kh++) {
            uint32_t ah[2][4], al[2][4];
#pragma unroll
            for (int mt = 0; mt < 2; mt++) {
                uint32_t off = swz(a_row + mt * 16, kh * 2 + a_chk);
                ldsm_x4(ah[mt], abase + off);
                ldsm_x4(al[mt], abase + 32768 + off);
            }
#pragma unroll
            for (int jj = 0; jj < 2; jj++) {
                uint32_t off = swz(b_row2 + jj * 16, kh * 2 + b_chk);
                uint32_t tb[4], tl[4];
                ldsm_x4(tb, bbase + off);
                ldsm_x4(tl, bbase + 8192 + off);
                const int j0 = 2 * jj, j1 = 2 * jj + 1;
                mma16816(acc2[0][j0], ah[0], tb + 0);
                mma16816(acc2[1][j0], ah[1], tb + 0);
                mma16816(acc2[0][j1], ah[0], tb + 2);
                mma16816(acc2[1][j1], ah[1], tb + 2);
                mma16816(acc2[0][j0], ah[0], tl + 0);
                mma16816(acc2[1][j0], ah[1], tl + 0);
                mma16816(acc2[0][j1], ah[0], tl + 2);
                mma16816(acc2[1][j1], ah[1], tl + 2);
                mma16816(acc2[0][j0], al[0], tb + 0);
                mma16816(acc2[1][j0], al[1], tb + 0);
                mma16816(acc2[0][j1], al[0], tb + 2);
                mma16816(acc2[1][j1], al[1], tb + 2);
            }
        }
        __syncthreads();
        if (kc + 2 < 8) load_B2(kc & 1, kc + 2);
    }

    // ---- epilogue: t2 fp32 [64 x 128] ----
    const int m_base = blockM + wm * 32 + (lane >> 2);
    const int n_base = wn * 32 + 2 * (lane & 3);
#pragma unroll
    for (int mt = 0; mt < 2; mt++) {
#pragma unroll
        for (int j = 0; j < 4; j++) {
            int n = n_base + 8 * j;
            float2 v0 = make_float2(acc2[mt][j][0], acc2[mt][j][1]);
            float2 v1 = make_float2(acc2[mt][j][2], acc2[mt][j][3]);
            int m = m_base + mt * 16;
            if (m < M)     *(float2*)(t2 + (size_t)m * 128 + n)       = v0;
            if (m + 8 < M) *(float2*)(t2 + (size_t)(m + 8) * 128 + n) = v1;
        }
    }
}

// ---------------- launch ----------------
extern "C" void kernel_launch(void* const* d_in, const int* in_sizes, int n_in,
                              void* d_out, int out_size) {
    const int*   cncpt = (const int*)d_in[0];
    const int*   src   = (const int*)d_in[1];
    const int*   dst   = (const int*)d_in[2];
    const float* emb   = (const float*)d_in[3];
    const float* W1    = (const float*)d_in[4];
    const float* b1    = (const float*)d_in[5];
    const float* W2    = (const float*)d_in[6];
    const float* b2    = (const float*)d_in[7];
    float* out = (float*)d_out;

    __nv_bfloat16 *a1h, *a1l, *w1th, *w1tl, *w2th, *w2tl;
    float *t2;
    int *csr_src, *csr_c;
    cudaGetSymbolAddress((void**)&a1h,  g_a1h);
    cudaGetSymbolAddress((void**)&a1l,  g_a1l);
    cudaGetSymbolAddress((void**)&t2,   g_t2);
    cudaGetSymbolAddress((void**)&w1th, g_w1th);
    cudaGetSymbolAddress((void**)&w1tl, g_w1tl);
    cudaGetSymbolAddress((void**)&w2th, g_w2th);
    cudaGetSymbolAddress((void**)&w2tl, g_w2tl);
    cudaGetSymbolAddress((void**)&csr_src, g_csr_src);
    cudaGetSymbolAddress((void**)&csr_c,   g_csr_c);

    const int SMEM12 = 96 * 1024;
    cudaFuncSetAttribute(fused_gemm12,
                         cudaFuncAttributeMaxDynamicSharedMemorySize, SMEM12);

    // ---- prep: zero degree + weight transpose/split (covers N_NODES) ----
    const int prep_n = (N_NODES > D_HID * D_IN ? N_NODES : D_HID * D_IN);
    prep_all<<<(prep_n + 255) / 256, 256>>>(W1, W2);

    // ---- build CSR (by dst) ----
    hist_dst<<<(N_EDGES / 2 + 255) / 256, 256>>>((const int2*)dst);
    scan_deg<<<1, 1024>>>();
    scatter_edges<<<(N_EDGES / 2 + 255) / 256, 256>>>(
        (const int2*)src, (const int2*)dst, cncpt);

    const int agg_blocks = (N_NODES * 32 + 255) / 256;

    // ---- layer 1 aggregation -> split bf16 planes (high-occupancy standalone) ----
    agg_csr<false, true><<<agg_blocks, 256>>>(
        csr_c, (const float4*)emb, nullptr, nullptr, a1h, a1l);

    // ---- fused GEMM1+GEMM2: t2 = relu(agg1 @ W1 + b1) @ W2 (h1 stays on-chip) ----
    fused_gemm12<<<(N_NODES + 63) / 64, 256, SMEM12>>>(
        a1h, a1l, w1th, w1tl, w2th, w2tl, b1, t2, N_NODES);

    // ---- layer 2 aggregation + bias + relu into d_out ----
    agg_csr<true, false><<<agg_blocks, 256>>>(
        csr_src, (const float4*)t2, b2, (float4*)out, nullptr, nullptr);
}

// round 13
// speedup vs baseline: 1.2031x; 1.0124x over previous
#include <cuda_runtime.h>
#include <cuda_bf16.h>
#include <cstdint>

#define N_NODES 50000
#define N_EDGES 800000
#define D_IN 128
#define D_HID 256
#define D_OUT 128

// ---------------- scratch (static device arrays; no allocation) ----------------
__device__ __nv_bfloat16 g_a1h[(size_t)N_NODES * D_IN];    // agg1 hi  12.8 MB
__device__ __nv_bfloat16 g_a1l[(size_t)N_NODES * D_IN];    // agg1 lo
__device__ float         g_t2[(size_t)N_NODES * D_OUT];    // 25.6 MB
__device__ __nv_bfloat16 g_w1th[D_HID * D_IN], g_w1tl[D_HID * D_IN];
__device__ __nv_bfloat16 g_w2th[D_OUT * D_HID], g_w2tl[D_OUT * D_HID];
__device__ int  g_deg[N_NODES];
__device__ int  g_off[N_NODES + 1];
__device__ int  g_rank[N_EDGES];
__device__ int2 g_csr[N_EDGES];      // {src node id, cncpt[src]} per CSR slot

// ================= small helpers =================
__device__ __forceinline__ uint32_t smem_u32(const void* p) {
    uint32_t a;
    asm("{ .reg .u64 t; cvta.to.shared.u64 t, %1; cvt.u32.u64 %0, t; }" : "=r"(a) : "l"(p));
    return a;
}

// split fp32 pair -> (hi bf16x2, lo bf16x2); low half of the b32 = first elem
__device__ __forceinline__ void split2(float a0, float a1, uint32_t& hi, uint32_t& lo) {
    asm("cvt.rn.bf16x2.f32 %0, %1, %2;" : "=r"(hi) : "f"(a1), "f"(a0));
    float h0 = __uint_as_float(hi << 16);
    float h1 = __uint_as_float(hi & 0xFFFF0000u);
    float l0 = a0 - h0, l1 = a1 - h1;
    asm("cvt.rn.bf16x2.f32 %0, %1, %2;" : "=r"(lo) : "f"(l1), "f"(l0));
}

__device__ __forceinline__ void ldsm_x4(uint32_t* r, uint32_t addr) {
    asm volatile("ldmatrix.sync.aligned.m8n8.x4.shared.b16 {%0,%1,%2,%3}, [%4];"
                 : "=r"(r[0]), "=r"(r[1]), "=r"(r[2]), "=r"(r[3]) : "r"(addr));
}

__device__ __forceinline__ void mma16816(float* d, const uint32_t* a, const uint32_t* b) {
    asm volatile("mma.sync.aligned.m16n8k16.row.col.f32.bf16.bf16.f32 "
                 "{%0,%1,%2,%3}, {%4,%5,%6,%7}, {%8,%9}, {%0,%1,%2,%3};"
                 : "+f"(d[0]), "+f"(d[1]), "+f"(d[2]), "+f"(d[3])
                 : "r"(a[0]), "r"(a[1]), "r"(a[2]), "r"(a[3]), "r"(b[0]), "r"(b[1]));
}

__device__ __forceinline__ void cp_async16(uint32_t dst, const void* src, int size) {
    asm volatile("cp.async.cg.shared.global [%0], [%1], 16, %2;"
                 :: "r"(dst), "l"(src), "r"(size) : "memory");
}

// swizzled smem byte offset within a plane: row stride 64B, chunk16 XOR (row>>1)&3
__device__ __forceinline__ uint32_t swz(int row, int chunk) {
    return (uint32_t)(row * 64 + ((chunk ^ ((row >> 1) & 3)) << 4));
}

// ================= CSR build =================
// histogram (2 edges/thread); records each edge's within-bucket rank
__global__ __launch_bounds__(256) void hist_dst(const int2* __restrict__ dst2) {
    int i = blockIdx.x * blockDim.x + threadIdx.x;
    if (i >= N_EDGES / 2) return;
    int2 d = dst2[i];
    int r0 = atomicAdd(&g_deg[d.x], 1);
    int r1 = atomicAdd(&g_deg[d.y], 1);
    *(int2*)&g_rank[2 * i] = make_int2(r0, r1);
}
__global__ __launch_bounds__(1024) void scan_deg() {
    __shared__ int sums[1024];
    const int CHUNK = (N_NODES + 1023) / 1024;
    int t = threadIdx.x;
    int lo = t * CHUNK;
    int hi = min(lo + CHUNK, N_NODES);
    int s = 0;
    for (int i = lo; i < hi; i++) s += g_deg[i];
    sums[t] = s;
    __syncthreads();
    for (int d = 1; d < 1024; d <<= 1) {
        int v = (t >= d) ? sums[t - d] : 0;
        __syncthreads();
        sums[t] += v;
        __syncthreads();
    }
    int running = sums[t] - s;
    for (int i = lo; i < hi; i++) {
        g_off[i] = running;
        running += g_deg[i];
    }
    if (t == 1023) g_off[N_NODES] = sums[1023];
}
// non-atomic scatter (2 edges/thread); single int2 payload store per edge
__global__ __launch_bounds__(256) void scatter_edges(
    const int2* __restrict__ src2, const int2* __restrict__ dst2,
    const int* __restrict__ cncpt)
{
    int i = blockIdx.x * blockDim.x + threadIdx.x;
    if (i >= N_EDGES / 2) return;
    int2 s = src2[i];
    int2 d = dst2[i];
    int2 r = *(const int2*)&g_rank[2 * i];
    int c0 = cncpt[s.x];
    int c1 = cncpt[s.y];
    g_csr[g_off[d.x] + r.x] = make_int2(s.x, c0);
    g_csr[g_off[d.y] + r.y] = make_int2(s.y, c1);
}

// ========== fused: zero degree + weight transpose/split (one launch) ==========
// grid must cover max(N_NODES, D_HID*D_IN) threads
__global__ void prep_all(const float* __restrict__ W1, const float* __restrict__ W2) {
    int i = blockIdx.x * blockDim.x + threadIdx.x;
    if (i < N_NODES) g_deg[i] = 0;
    if (i < D_HID * D_IN) {                  // W1^T [256][128]
        int n = i / D_IN, k = i % D_IN;
        float v = W1[(size_t)k * D_HID + n];
        __nv_bfloat16 h = __float2bfloat16_rn(v);
        g_w1th[i] = h;
        g_w1tl[i] = __float2bfloat16_rn(v - __bfloat162float(h));
    }
    if (i < D_OUT * D_HID) {                 // W2^T [128][256]
        int n = i / D_HID, k = i % D_HID;
        float v = W2[(size_t)k * D_OUT + n];
        __nv_bfloat16 h = __float2bfloat16_rn(v);
        g_w2th[i] = h;
        g_w2tl[i] = __float2bfloat16_rn(v - __bfloat162float(h));
    }
}

// ================= CSR aggregation: warp per node, no atomics =================
// FIELD 0: gather by .x (src id). FIELD 1: gather by .y (concept id).
// SPLIT: write hi/lo bf16 planes. else: fp32 out (+bias+relu if EPI).
template<int FIELD, bool EPI, bool SPLIT>
__global__ __launch_bounds__(256) void agg_csr(
    const float4* __restrict__ rows,
    const float* __restrict__ bias, float4* __restrict__ outf,
    __nv_bfloat16* __restrict__ oh, __nv_bfloat16* __restrict__ ol)
{
    int w = (blockIdx.x * blockDim.x + threadIdx.x) >> 5;
    if (w >= N_NODES) return;
    int lane = threadIdx.x & 31;
    int beg = g_off[w], end = g_off[w + 1];

    float4 acc = make_float4(0.f, 0.f, 0.f, 0.f);
    int j = beg;
    for (; j + 16 <= end; j += 16) {
        int s[16];
#pragma unroll
        for (int q = 0; q < 16; q++) {
            int2 e = g_csr[j + q];
            s[q] = FIELD ? e.y : e.x;
        }
        float4 v[16];
#pragma unroll
        for (int q = 0; q < 16; q++) v[q] = rows[(size_t)s[q] * 32 + lane];
#pragma unroll
        for (int q = 0; q < 16; q++) {
            acc.x += v[q].x; acc.y += v[q].y; acc.z += v[q].z; acc.w += v[q].w;
        }
    }
    for (; j + 4 <= end; j += 4) {
        int s[4];
#pragma unroll
        for (int q = 0; q < 4; q++) {
            int2 e = g_csr[j + q];
            s[q] = FIELD ? e.y : e.x;
        }
        float4 v[4];
#pragma unroll
        for (int q = 0; q < 4; q++) v[q] = rows[(size_t)s[q] * 32 + lane];
#pragma unroll
        for (int q = 0; q < 4; q++) {
            acc.x += v[q].x; acc.y += v[q].y; acc.z += v[q].z; acc.w += v[q].w;
        }
    }
    for (; j < end; j++) {
        int2 e = g_csr[j];
        float4 v = rows[(size_t)(FIELD ? e.y : e.x) * 32 + lane];
        acc.x += v.x; acc.y += v.y; acc.z += v.z; acc.w += v.w;
    }
    if (EPI) {
        float4 b = ((const float4*)bias)[lane];
        acc.x = fmaxf(acc.x + b.x, 0.f);
        acc.y = fmaxf(acc.y + b.y, 0.f);
        acc.z = fmaxf(acc.z + b.z, 0.f);
        acc.w = fmaxf(acc.w + b.w, 0.f);
    }
    if (SPLIT) {
        uint32_t h0, l0, h1, l1;
        split2(acc.x, acc.y, h0, l0);
        split2(acc.z, acc.w, h1, l1);
        size_t off = (size_t)w * 128 + lane * 4;
        *(uint2*)(oh + off) = make_uint2(h0, h1);
        *(uint2*)(ol + off) = make_uint2(l0, l1);
    } else {
        outf[(size_t)w * 32 + lane] = acc;
    }
}

// ========== FUSED GEMM1+GEMM2: t2[64x128] = relu(A1[64x128]@W1T^T + b1) @ W2T^T ==========
// Phase A: h = relu(A1 @ W1T^T + b1), acc in registers (A1 smem-resident, W1
// double-buffered). h restaged to smem as split-bf16 K-chunk planes. Phase B:
// t2 = h @ W2T^T with W2 double-buffered. h1 never touches global memory.
// smem (96KB): phase A [A1 hi16K|lo16K][W1 2x(hi16K|lo16K)]
//              phase B [H hi32K|lo32K][W2 2x(hi8K|lo8K)]
__global__ __launch_bounds__(256, 2) void fused_gemm12(
    const __nv_bfloat16* __restrict__ A1h, const __nv_bfloat16* __restrict__ A1l,
    const __nv_bfloat16* __restrict__ B1h, const __nv_bfloat16* __restrict__ B1l,
    const __nv_bfloat16* __restrict__ B2h, const __nv_bfloat16* __restrict__ B2l,
    const float* __restrict__ bias1, float* __restrict__ t2, int M)
{
    constexpr int B1_OFF = 32768;
    constexpr int B2_OFF = 65536;
    extern __shared__ __align__(16) char smem[];
    const uint32_t sb0 = smem_u32(smem);

    const int tid  = threadIdx.x;
    const int wid  = tid >> 5;
    const int lane = tid & 31;
    const int wm   = wid & 1;              // 2 warps along M (32 rows each)
    const int wn   = wid >> 1;             // 4 warps along N
    const int blockM = blockIdx.x * 64;

    const int a_row = wm * 32 + (lane & 15);
    const int a_chk = lane >> 4;
    const int b_row1 = wn * 64 + ((lane >> 4) << 3) + (lane & 7);   // phase A (256 rows)
    const int b_row2 = wn * 32 + ((lane >> 4) << 3) + (lane & 7);   // phase B (128 rows)
    const int b_chk = (lane >> 3) & 1;

    // ---- group 1: A1 tile 64x128 hi/lo (2048 x 16B) ----
    {
#pragma unroll
        for (int i = 0; i < 8; i++) {
            int g = i * 256 + tid;
            int p = g >> 10;
            int idx = g & 1023;
            int r = idx >> 4, q = idx & 15;
            int gm = blockM + r;
            int cm = gm < M ? gm : 0;
            int size = gm < M ? 16 : 0;
            const __nv_bfloat16* src = (p ? A1l : A1h) + (size_t)cm * 128 + q * 8;
            cp_async16(sb0 + (uint32_t)(p * 16384 + (q >> 2) * 4096) + swz(r, q & 3),
                       src, size);
        }
        asm volatile("cp.async.commit_group;" ::: "memory");
    }

    // ---- W1 stage loader: 256 rows x 64B x 2 planes (2048 x 16B) ----
    auto load_B1 = [&](int s, int kc) {
        uint32_t sb = sb0 + B1_OFF + (uint32_t)s * 32768;
#pragma unroll
        for (int i = 0; i < 8; i++) {
            int g = i * 256 + tid;
            int p = g >> 10;
            int idx = g & 1023;
            int row = idx >> 2, c = idx & 3;
            const __nv_bfloat16* src = (p ? B1l : B1h) + (size_t)row * 128 + kc * 32 + c * 8;
            cp_async16(sb + (uint32_t)p * 16384 + swz(row, c), src, 16);
        }
        asm volatile("cp.async.commit_group;" ::: "memory");
    };
    load_B1(0, 0);
    load_B1(1, 1);

    float acc1[2][8][4];
#pragma unroll
    for (int mt = 0; mt < 2; mt++)
#pragma unroll
        for (int j = 0; j < 8; j++)
#pragma unroll
            for (int q = 0; q < 4; q++) acc1[mt][j][q] = 0.f;

    // ---- Phase A mainloop: 4 K-chunks ----
    for (int kc = 0; kc < 4; kc++) {
        if (kc < 3) asm volatile("cp.async.wait_group 1;" ::: "memory");
        else        asm volatile("cp.async.wait_group 0;" ::: "memory");
        __syncthreads();

        const uint32_t abase = sb0 + (uint32_t)(kc * 4096);
        const uint32_t bbase = sb0 + B1_OFF + (uint32_t)((kc & 1) * 32768);
#pragma unroll
        for (int kh = 0; kh < 2; kh++) {
            uint32_t ah[2][4], al[2][4];
#pragma unroll
            for (int mt = 0; mt < 2; mt++) {
                uint32_t off = swz(a_row + mt * 16, kh * 2 + a_chk);
                ldsm_x4(ah[mt], abase + off);
                ldsm_x4(al[mt], abase + 16384 + off);
            }
#pragma unroll
            for (int jj = 0; jj < 4; jj++) {
                uint32_t off = swz(b_row1 + jj * 16, kh * 2 + b_chk);
                uint32_t tb[4], tl[4];
                ldsm_x4(tb, bbase + off);
                ldsm_x4(tl, bbase + 16384 + off);
                const int j0 = 2 * jj, j1 = 2 * jj + 1;
                mma16816(acc1[0][j0], ah[0], tb + 0);
                mma16816(acc1[1][j0], ah[1], tb + 0);
                mma16816(acc1[0][j1], ah[0], tb + 2);
                mma16816(acc1[1][j1], ah[1], tb + 2);
                mma16816(acc1[0][j0], ah[0], tl + 0);
                mma16816(acc1[1][j0], ah[1], tl + 0);
                mma16816(acc1[0][j1], ah[0], tl + 2);
                mma16816(acc1[1][j1], ah[1], tl + 2);
                mma16816(acc1[0][j0], al[0], tb + 0);
                mma16816(acc1[1][j0], al[1], tb + 0);
                mma16816(acc1[0][j1], al[0], tb + 2);
                mma16816(acc1[1][j1], al[1], tb + 2);
            }
        }
        __syncthreads();
        if (kc + 2 < 4) load_B1(kc & 1, kc + 2);
    }

    // ---- W2 stage loader: 128 rows x 64B x 2 planes (1024 x 16B) ----
    auto load_B2 = [&](int s, int kc) {
        uint32_t sb = sb0 + B2_OFF + (uint32_t)s * 16384;
#pragma unroll
        for (int i = 0; i < 4; i++) {
            int g = i * 256 + tid;
            int p = g >> 9;
            int idx = g & 511;
            int row = idx >> 2, c = idx & 3;
            const __nv_bfloat16* src = (p ? B2l : B2h) + (size_t)row * 256 + kc * 32 + c * 8;
            cp_async16(sb + (uint32_t)p * 8192 + swz(row, c), src, 16);
        }
        asm volatile("cp.async.commit_group;" ::: "memory");
    };
    load_B2(0, 0);
    load_B2(1, 1);

    // ---- transition: bias+relu, restage h as split-bf16 K-chunk planes ----
    {
        const int m_loc = wm * 32 + (lane >> 2);
        const int n_loc = wn * 64 + 2 * (lane & 3);
#pragma unroll
        for (int mt = 0; mt < 2; mt++) {
#pragma unroll
            for (int j = 0; j < 8; j++) {
                int n = n_loc + 8 * j;
                float bb0 = bias1[n], bb1 = bias1[n + 1];
                float2 v0 = make_float2(fmaxf(acc1[mt][j][0] + bb0, 0.f),
                                        fmaxf(acc1[mt][j][1] + bb1, 0.f));
                float2 v1 = make_float2(fmaxf(acc1[mt][j][2] + bb0, 0.f),
                                        fmaxf(acc1[mt][j][3] + bb1, 0.f));
                uint32_t kc2 = (uint32_t)(n >> 5) * 4096;
                uint32_t bc = (uint32_t)(n & 31) * 2;
                uint32_t chk = bc >> 4, rem = bc & 12;
                int r0 = m_loc + mt * 16, r1 = r0 + 8;
                uint32_t h, l;
                split2(v0.x, v0.y, h, l);
                *(uint32_t*)(smem + kc2 + swz(r0, chk) + rem) = h;
                *(uint32_t*)(smem + 32768 + kc2 + swz(r0, chk) + rem) = l;
                split2(v1.x, v1.y, h, l);
                *(uint32_t*)(smem + kc2 + swz(r1, chk) + rem) = h;
                *(uint32_t*)(smem + 32768 + kc2 + swz(r1, chk) + rem) = l;
            }
        }
    }
    __syncthreads();

    // ---- Phase B mainloop: 8 K-chunks ----
    float acc2[2][4][4];
#pragma unroll
    for (int mt = 0; mt < 2; mt++)
#pragma unroll
        for (int j = 0; j < 4; j++)
#pragma unroll
            for (int q = 0; q < 4; q++) acc2[mt][j][q] = 0.f;

    for (int kc = 0; kc < 8; kc++) {
        if (kc < 7) asm volatile("cp.async.wait_group 1;" ::: "memory");
        else        asm volatile("cp.async.wait_group 0;" ::: "memory");
        __syncthreads();

        const uint32_t abase = sb0 + (uint32_t)(kc * 4096);
        const uint32_t bbase = sb0 + B2_OFF + (uint32_t)((kc & 1) * 16384);
#pragma unroll
        for (int kh = 0; kh < 2; kh++) {
            uint32_t ah[2][4], al[2][4];
#pragma unroll
            for (int mt = 0; mt < 2; mt++) {
                uint32_t off = swz(a_row + mt * 16, kh * 2 + a_chk);
                ldsm_x4(ah[mt], abase + off);
                ldsm_x4(al[mt], abase + 32768 + off);
            }
#pragma unroll
            for (int jj = 0; jj < 2; jj++) {
                uint32_t off = swz(b_row2 + jj * 16, kh * 2 + b_chk);
                uint32_t tb[4], tl[4];
                ldsm_x4(tb, bbase + off);
                ldsm_x4(tl, bbase + 8192 + off);
                const int j0 = 2 * jj, j1 = 2 * jj + 1;
                mma16816(acc2[0][j0], ah[0], tb + 0);
                mma16816(acc2[1][j0], ah[1], tb + 0);
                mma16816(acc2[0][j1], ah[0], tb + 2);
                mma16816(acc2[1][j1], ah[1], tb + 2);
                mma16816(acc2[0][j0], ah[0], tl + 0);
                mma16816(acc2[1][j0], ah[1], tl + 0);
                mma16816(acc2[0][j1], ah[0], tl + 2);
                mma16816(acc2[1][j1], ah[1], tl + 2);
                mma16816(acc2[0][j0], al[0], tb + 0);
                mma16816(acc2[1][j0], al[1], tb + 0);
                mma16816(acc2[0][j1], al[0], tb + 2);
                mma16816(acc2[1][j1], al[1], tb + 2);
            }
        }
        __syncthreads();
        if (kc + 2 < 8) load_B2(kc & 1, kc + 2);
    }

    // ---- epilogue: t2 fp32 [64 x 128] ----
    const int m_base = blockM + wm * 32 + (lane >> 2);
    const int n_base = wn * 32 + 2 * (lane & 3);
#pragma unroll
    for (int mt = 0; mt < 2; mt++) {
#pragma unroll
        for (int j = 0; j < 4; j++) {
            int n = n_base + 8 * j;
            float2 v0 = make_float2(acc2[mt][j][0], acc2[mt][j][1]);
            float2 v1 = make_float2(acc2[mt][j][2], acc2[mt][j][3]);
            int m = m_base + mt * 16;
            if (m < M)     *(float2*)(t2 + (size_t)m * 128 + n)       = v0;
            if (m + 8 < M) *(float2*)(t2 + (size_t)(m + 8) * 128 + n) = v1;
        }
    }
}

// ---------------- launch ----------------
extern "C" void kernel_launch(void* const* d_in, const int* in_sizes, int n_in,
                              void* d_out, int out_size) {
    const int*   cncpt = (const int*)d_in[0];
    const int*   src   = (const int*)d_in[1];
    const int*   dst   = (const int*)d_in[2];
    const float* emb   = (const float*)d_in[3];
    const float* W1    = (const float*)d_in[4];
    const float* b1    = (const float*)d_in[5];
    const float* W2    = (const float*)d_in[6];
    const float* b2    = (const float*)d_in[7];
    float* out = (float*)d_out;

    __nv_bfloat16 *a1h, *a1l, *w1th, *w1tl, *w2th, *w2tl;
    float *t2;
    cudaGetSymbolAddress((void**)&a1h,  g_a1h);
    cudaGetSymbolAddress((void**)&a1l,  g_a1l);
    cudaGetSymbolAddress((void**)&t2,   g_t2);
    cudaGetSymbolAddress((void**)&w1th, g_w1th);
    cudaGetSymbolAddress((void**)&w1tl, g_w1tl);
    cudaGetSymbolAddress((void**)&w2th, g_w2th);
    cudaGetSymbolAddress((void**)&w2tl, g_w2tl);

    const int SMEM12 = 96 * 1024;
    cudaFuncSetAttribute(fused_gemm12,
                         cudaFuncAttributeMaxDynamicSharedMemorySize, SMEM12);

    // ---- prep: zero degree + weight transpose/split (covers N_NODES) ----
    const int prep_n = (N_NODES > D_HID * D_IN ? N_NODES : D_HID * D_IN);
    prep_all<<<(prep_n + 255) / 256, 256>>>(W1, W2);

    // ---- build CSR (by dst) ----
    hist_dst<<<(N_EDGES / 2 + 255) / 256, 256>>>((const int2*)dst);
    scan_deg<<<1, 1024>>>();
    scatter_edges<<<(N_EDGES / 2 + 255) / 256, 256>>>(
        (const int2*)src, (const int2*)dst, cncpt);

    const int agg_blocks = (N_NODES * 32 + 255) / 256;

    // ---- layer 1 aggregation (gather by concept id) -> split bf16 planes ----
    agg_csr<1, false, true><<<agg_blocks, 256>>>(
        (const float4*)emb, nullptr, nullptr, a1h, a1l);

    // ---- fused GEMM1+GEMM2: t2 = relu(agg1 @ W1 + b1) @ W2 (h1 stays on-chip) ----
    fused_gemm12<<<(N_NODES + 63) / 64, 256, SMEM12>>>(
        a1h, a1l, w1th, w1tl, w2th, w2tl, b1, t2, N_NODES);

    // ---- layer 2 aggregation (gather by src id) + bias + relu into d_out ----
    agg_csr<0, true, false><<<agg_blocks, 256>>>(
        (const float4*)t2, b2, (float4*)out, nullptr, nullptr);
}